// round 15
// baseline (speedup 1.0000x reference)
#include <cuda_runtime.h>
#include <cuda_bf16.h>
#include <math.h>
#include <stdint.h>

#define NB 32
#define NS 1024
#define NIN 16
#define NE 128
#define NHID 256
#define NDH 32
#define TOK (NB * NS)          /* 32768 */
#define EPSV 1e-5f
#define HSTRIDE (NS * NDH)     /* 32768 elems per (b,head) */

/* ---------------- scratch ---------------- */
__device__ float g_poolp[NB * 8 * NE];
__device__ __nv_bfloat16 g_hbf[TOK * NE];
__device__ __nv_bfloat16 g_attnbf[TOK * NE];
__device__ __nv_bfloat16 g_qh[NB * 4 * HSTRIDE];
__device__ __nv_bfloat16 g_kh[NB * 4 * HSTRIDE];
__device__ __nv_bfloat16 g_vh[NB * 4 * HSTRIDE];
#define WTILE (128 * 128)
__device__ __nv_bfloat16 g_wh[3 * 6 * WTILE];   /* bf16 weights */

/* ================= common helpers ================= */
__device__ __forceinline__ uint32_t smem_u32(const void* p) {
    uint32_t a;
    asm("{ .reg .u64 t; cvta.to.shared.u64 t, %1; cvt.u32.u64 %0, t; }" : "=r"(a) : "l"(p));
    return a;
}
__device__ __forceinline__ void ldsm4(uint32_t* r, uint32_t addr) {
    asm volatile("ldmatrix.sync.aligned.m8n8.x4.shared.b16 {%0,%1,%2,%3}, [%4];"
                 : "=r"(r[0]), "=r"(r[1]), "=r"(r[2]), "=r"(r[3]) : "r"(addr));
}
__device__ __forceinline__ void ldsm4t(uint32_t* r, uint32_t addr) {
    asm volatile("ldmatrix.sync.aligned.m8n8.x4.trans.shared.b16 {%0,%1,%2,%3}, [%4];"
                 : "=r"(r[0]), "=r"(r[1]), "=r"(r[2]), "=r"(r[3]) : "r"(addr));
}
__device__ __forceinline__ void mma16816(float* c, const uint32_t* a, const uint32_t* b) {
    asm volatile(
        "mma.sync.aligned.m16n8k16.row.col.f32.bf16.bf16.f32 "
        "{%0,%1,%2,%3}, {%4,%5,%6,%7}, {%8,%9}, {%0,%1,%2,%3};"
        : "+f"(c[0]), "+f"(c[1]), "+f"(c[2]), "+f"(c[3])
        : "r"(a[0]), "r"(a[1]), "r"(a[2]), "r"(a[3]), "r"(b[0]), "r"(b[1]));
}
__device__ __forceinline__ float ex2f(float x) {
    float r; asm("ex2.approx.f32 %0, %1;" : "=f"(r) : "f"(x)); return r;
}
__device__ __forceinline__ uint32_t packbf(float lo, float hi) {
    uint32_t r;
    asm("cvt.rn.bf16x2.f32 %0, %1, %2;" : "=r"(r) : "f"(hi), "f"(lo));
    return r;
}
__device__ __forceinline__ float bf2f(__nv_bfloat16 v) { return __bfloat162float(v); }
__device__ __forceinline__ void cpa16(uint32_t dst, const void* src) {
    asm volatile("cp.async.cg.shared.global [%0], [%1], 16;" :: "r"(dst), "l"(src));
}
__device__ __forceinline__ void cpcommit() { asm volatile("cp.async.commit_group;"); }
template <int N>
__device__ __forceinline__ void cpwait() {
    asm volatile("cp.async.wait_group %0;" :: "n"(N) : "memory");
}

/* ================= GEMM building blocks ================= */
#define TROW 136
#define TILE_BYTES (128 * TROW * 2)   /* 34816 */
#define SMEM_MMA (3 * TILE_BYTES)     /* fused3: A + 2 W slots */
#define SMEM_QKV (2 * TILE_BYTES)     /* qkv1: A + 1 W slot */

__device__ __forceinline__ void load_A(const __nv_bfloat16* __restrict__ A,
                                       uint32_t sbase, int tid) {
#pragma unroll
    for (int i = 0; i < 8; i++) {
        const int idx = tid + i * 256;
        const int row = idx >> 4;
        const int c16 = idx & 15;
        cpa16(sbase + (uint32_t)(row * 272 + c16 * 16), A + row * 128 + c16 * 8);
    }
}
__device__ __forceinline__ void load_Wslot(const __nv_bfloat16* __restrict__ W,
                                           uint32_t slotbase, int tid) {
#pragma unroll
    for (int i = 0; i < 8; i++) {
        const int idx = tid + i * 256;
        const int row = idx >> 4;
        const int c16 = idx & 15;
        cpa16(slotbase + (uint32_t)(row * 272 + c16 * 16), W + row * 128 + c16 * 8);
    }
    cpcommit();
}
/* single K-pass (bf16 W): interleaved ldsm->2xMMA */
__device__ __forceinline__ void mma_pass(uint32_t sbase, uint32_t wbase,
                                         int tid, float acc[16][4]) {
    const int w = tid >> 5;
    const int lane = tid & 31;
    const int mat = lane >> 3;
    const int r8 = lane & 7;
#pragma unroll
    for (int kc = 0; kc < 8; kc++) {
        const int k0 = kc * 16;
        uint32_t afr[4];
        ldsm4(afr, sbase + ((w * 16 + (mat & 1) * 8 + r8) * TROW +
                            k0 + (mat >> 1) * 8) * 2);
#pragma unroll
        for (int nt2 = 0; nt2 < 8; nt2++) {
            uint32_t br[4];
            ldsm4(br, wbase + ((nt2 * 16 + (mat >> 1) * 8 + r8) * TROW +
                               k0 + (mat & 1) * 8) * 2);
            mma16816(acc[2 * nt2], afr, br);
            mma16816(acc[2 * nt2 + 1], afr, br + 2);
        }
    }
}

/* ---------- qkv GEMM: one CTA per (output x, m-tile) — max parallelism ---- */
__global__ __launch_bounds__(256, 2) void gemm_qkv1_kernel(
        const __nv_bfloat16* __restrict__ A, const __nv_bfloat16* __restrict__ whb,
        const float* __restrict__ bias,
        __nv_bfloat16* __restrict__ qh, __nv_bfloat16* __restrict__ kh,
        __nv_bfloat16* __restrict__ vh) {
    extern __shared__ char smem[];
    const uint32_t sbase = smem_u32(smem);
    const int tid = threadIdx.x;
    const int x = blockIdx.x;               /* 0=Q 1=K 2=V */
    const int m0 = blockIdx.y * 128;
    const int lane = tid & 31;
    const int w = tid >> 5;
    const int g = lane >> 2;
    const int tig = lane & 3;
    const int tok0 = m0 + w * 16 + g;
    const float qscale = 1.4426950408889634f * 0.17677669529663687f;

    load_A(A + (size_t)m0 * 128, sbase, tid);
    load_Wslot(whb + (size_t)x * WTILE, sbase + TILE_BYTES, tid);
    cpwait<0>();
    __syncthreads();

    float acc[16][4];
#pragma unroll
    for (int i = 0; i < 16; i++)
#pragma unroll
        for (int j = 0; j < 4; j++) acc[i][j] = 0.0f;
    mma_pass(sbase, sbase + TILE_BYTES, tid, acc);

    __nv_bfloat16* dhi = (x == 0) ? qh : (x == 1) ? kh : vh;
#pragma unroll
    for (int nt = 0; nt < 16; nt++) {
        const int cc = nt * 8 + tig * 2;
        float2 b01 = *(const float2*)&bias[x * 128 + cc];
        float v00 = acc[nt][0] + b01.x, v01 = acc[nt][1] + b01.y;
        float v10 = acc[nt][2] + b01.x, v11 = acc[nt][3] + b01.y;
        if (x == 0) { v00 *= qscale; v01 *= qscale; v10 *= qscale; v11 *= qscale; }
        const int hh = cc >> 5;
        const int d = cc & 31;
        const size_t i0 = ((size_t)((tok0 >> 10) * 4 + hh) << 15) +
                          (tok0 & 1023) * 32 + d;
        const size_t i1 = i0 + 8 * 32;
        *(uint32_t*)&dhi[i0] = packbf(v00, v01);
        *(uint32_t*)&dhi[i1] = packbf(v10, v11);
    }
}

/* ---------- fused layer tail (unchanged from R14, validated) ---------- */
__global__ __launch_bounds__(256, 2) void gemm_fused3_kernel(
        const __nv_bfloat16* __restrict__ attnA, const __nv_bfloat16* __restrict__ whb,
        const float* __restrict__ ob,
        const float* __restrict__ fb1, const float* __restrict__ fb2,
        const float* __restrict__ l1g, const float* __restrict__ l1b,
        const float* __restrict__ l2g, const float* __restrict__ l2b,
        __nv_bfloat16* __restrict__ hio) {
    extern __shared__ char smem[];
    const uint32_t sbase = smem_u32(smem);
    const int tid = threadIdx.x;
    const int m0 = blockIdx.y * 128;
    const int lane = tid & 31;
    const int w = tid >> 5;
    const int g = lane >> 2;
    const int tig = lane & 3;
    const int row0 = m0 + w * 16 + g;
    const int row1 = row0 + 8;
    const int srow0 = w * 16 + g;
    const int srow1 = srow0 + 8;

    float acc[16][4];
    uint32_t h2p[32];

    load_A(attnA + (size_t)m0 * 128, sbase, tid);
    load_Wslot(whb + 3 * WTILE, sbase + TILE_BYTES, tid);        /* G1 = A + Wo */
    load_Wslot(whb + 4 * WTILE, sbase + 2 * TILE_BYTES, tid);    /* G2 = W_ffn1 */
    cpwait<1>();
    __syncthreads();

    /* ===== stage 1: out-proj + resid + LN ===== */
#pragma unroll
    for (int i = 0; i < 16; i++)
#pragma unroll
        for (int j = 0; j < 4; j++) acc[i][j] = 0.0f;
    mma_pass(sbase, sbase + TILE_BYTES, tid, acc);
    __syncthreads();
    load_Wslot(whb + 5 * WTILE, sbase + TILE_BYTES, tid);        /* G3 = W_ffn2 */

    {
        float s0 = 0.0f, s1 = 0.0f;
#pragma unroll
        for (int nt = 0; nt < 16; nt++) {
            const int cc = nt * 8 + tig * 2;
            float2 b01 = *(const float2*)&ob[cc];
            __nv_bfloat162 r0 = *(const __nv_bfloat162*)&hio[(size_t)row0 * NE + cc];
            __nv_bfloat162 r1 = *(const __nv_bfloat162*)&hio[(size_t)row1 * NE + cc];
            acc[nt][0] += b01.x + bf2f(r0.x); acc[nt][1] += b01.y + bf2f(r0.y);
            acc[nt][2] += b01.x + bf2f(r1.x); acc[nt][3] += b01.y + bf2f(r1.y);
            s0 += acc[nt][0] + acc[nt][1];
            s1 += acc[nt][2] + acc[nt][3];
        }
        s0 += __shfl_xor_sync(0xffffffffu, s0, 1);
        s0 += __shfl_xor_sync(0xffffffffu, s0, 2);
        s1 += __shfl_xor_sync(0xffffffffu, s1, 1);
        s1 += __shfl_xor_sync(0xffffffffu, s1, 2);
        const float mean0 = s0 * (1.0f / NE), mean1 = s1 * (1.0f / NE);
        float q0 = 0.0f, q1 = 0.0f;
#pragma unroll
        for (int nt = 0; nt < 16; nt++) {
            const float d0 = acc[nt][0] - mean0, d1 = acc[nt][1] - mean0;
            const float d2 = acc[nt][2] - mean1, d3 = acc[nt][3] - mean1;
            q0 += d0 * d0 + d1 * d1;
            q1 += d2 * d2 + d3 * d3;
        }
        q0 += __shfl_xor_sync(0xffffffffu, q0, 1);
        q0 += __shfl_xor_sync(0xffffffffu, q0, 2);
        q1 += __shfl_xor_sync(0xffffffffu, q1, 1);
        q1 += __shfl_xor_sync(0xffffffffu, q1, 2);
        const float rstd0 = rsqrtf(q0 * (1.0f / NE) + EPSV);
        const float rstd1 = rsqrtf(q1 * (1.0f / NE) + EPSV);
#pragma unroll
        for (int nt = 0; nt < 16; nt++) {
            const int cc = nt * 8 + tig * 2;
            float2 gg = *(const float2*)&l1g[cc];
            float2 bb = *(const float2*)&l1b[cc];
            h2p[2 * nt] = packbf((acc[nt][0] - mean0) * rstd0 * gg.x + bb.x,
                                 (acc[nt][1] - mean0) * rstd0 * gg.y + bb.y);
            h2p[2 * nt + 1] = packbf((acc[nt][2] - mean1) * rstd1 * gg.x + bb.x,
                                     (acc[nt][3] - mean1) * rstd1 * gg.y + bb.y);
            *(uint32_t*)(smem + (srow0 * TROW + cc) * 2) = h2p[2 * nt];
            *(uint32_t*)(smem + (srow1 * TROW + cc) * 2) = h2p[2 * nt + 1];
        }
    }
    __syncthreads();            /* h2 visible */
    cpwait<1>();                /* W_ffn1 ready (W_ffn2 in flight) */
    __syncthreads();

    /* ===== stage 2: ffn1 + relu ===== */
#pragma unroll
    for (int i = 0; i < 16; i++)
#pragma unroll
        for (int j = 0; j < 4; j++) acc[i][j] = 0.0f;
    mma_pass(sbase, sbase + 2 * TILE_BYTES, tid, acc);
    __syncthreads();

#pragma unroll
    for (int nt = 0; nt < 16; nt++) {
        const int cc = nt * 8 + tig * 2;
        float2 b01 = *(const float2*)&fb1[cc];
        *(uint32_t*)(smem + (srow0 * TROW + cc) * 2) =
            packbf(fmaxf(acc[nt][0] + b01.x, 0.0f), fmaxf(acc[nt][1] + b01.y, 0.0f));
        *(uint32_t*)(smem + (srow1 * TROW + cc) * 2) =
            packbf(fmaxf(acc[nt][2] + b01.x, 0.0f), fmaxf(acc[nt][3] + b01.y, 0.0f));
    }
    __syncthreads();
    cpwait<0>();                /* W_ffn2 ready */
    __syncthreads();

    /* ===== stage 3: ffn2 + resid(h2) + LN -> hio ===== */
#pragma unroll
    for (int i = 0; i < 16; i++)
#pragma unroll
        for (int j = 0; j < 4; j++) acc[i][j] = 0.0f;
    mma_pass(sbase, sbase + TILE_BYTES, tid, acc);

    {
        float s0 = 0.0f, s1 = 0.0f;
#pragma unroll
        for (int nt = 0; nt < 16; nt++) {
            const int cc = nt * 8 + tig * 2;
            float2 b01 = *(const float2*)&fb2[cc];
            const __nv_bfloat162 r0 = *(const __nv_bfloat162*)&h2p[2 * nt];
            const __nv_bfloat162 r1 = *(const __nv_bfloat162*)&h2p[2 * nt + 1];
            acc[nt][0] += b01.x + bf2f(r0.x); acc[nt][1] += b01.y + bf2f(r0.y);
            acc[nt][2] += b01.x + bf2f(r1.x); acc[nt][3] += b01.y + bf2f(r1.y);
            s0 += acc[nt][0] + acc[nt][1];
            s1 += acc[nt][2] + acc[nt][3];
        }
        s0 += __shfl_xor_sync(0xffffffffu, s0, 1);
        s0 += __shfl_xor_sync(0xffffffffu, s0, 2);
        s1 += __shfl_xor_sync(0xffffffffu, s1, 1);
        s1 += __shfl_xor_sync(0xffffffffu, s1, 2);
        const float mean0 = s0 * (1.0f / NE), mean1 = s1 * (1.0f / NE);
        float q0 = 0.0f, q1 = 0.0f;
#pragma unroll
        for (int nt = 0; nt < 16; nt++) {
            const float d0 = acc[nt][0] - mean0, d1 = acc[nt][1] - mean0;
            const float d2 = acc[nt][2] - mean1, d3 = acc[nt][3] - mean1;
            q0 += d0 * d0 + d1 * d1;
            q1 += d2 * d2 + d3 * d3;
        }
        q0 += __shfl_xor_sync(0xffffffffu, q0, 1);
        q0 += __shfl_xor_sync(0xffffffffu, q0, 2);
        q1 += __shfl_xor_sync(0xffffffffu, q1, 1);
        q1 += __shfl_xor_sync(0xffffffffu, q1, 2);
        const float rstd0 = rsqrtf(q0 * (1.0f / NE) + EPSV);
        const float rstd1 = rsqrtf(q1 * (1.0f / NE) + EPSV);
#pragma unroll
        for (int nt = 0; nt < 16; nt++) {
            const int cc = nt * 8 + tig * 2;
            float2 gg = *(const float2*)&l2g[cc];
            float2 bb = *(const float2*)&l2b[cc];
            *(uint32_t*)&hio[(size_t)row0 * NE + cc] =
                packbf((acc[nt][0] - mean0) * rstd0 * gg.x + bb.x,
                       (acc[nt][1] - mean0) * rstd0 * gg.y + bb.y);
            *(uint32_t*)&hio[(size_t)row1 * NE + cc] =
                packbf((acc[nt][2] - mean1) * rstd1 * gg.x + bb.x,
                       (acc[nt][3] - mean1) * rstd1 * gg.y + bb.y);
        }
    }
}

/* ================= MMA flash attention: 2 q-tiles/CTA (unchanged R14) ====== */
#define AQ_BYTES 10240                  /* 128 rows x 80B */
#define KVBUF 20480
#define ATT_SMEM (AQ_BYTES + 2 * KVBUF) /* 51200, dynamic */

__global__ __launch_bounds__(256, 2) void attn_mma_kernel(
        const __nv_bfloat16* __restrict__ qh, const __nv_bfloat16* __restrict__ kh,
        const __nv_bfloat16* __restrict__ vh, __nv_bfloat16* __restrict__ outb) {
    extern __shared__ char smem[];
    const uint32_t sbase = smem_u32(smem);

    const int blk = blockIdx.x;        /* b(32) x hh(4) x qt2(8) */
    const int qt2 = blk & 7;
    const int hh = (blk >> 3) & 3;
    const int b = blk >> 5;
    const int tid = threadIdx.x;
    const int w = tid >> 5;
    const int lane = tid & 31;
    const int mat = lane >> 3;
    const int r8 = lane & 7;
    const int g = lane >> 2;
    const int tig = lane & 3;

    const size_t hbase = (size_t)(b * 4 + hh) * HSTRIDE;

#pragma unroll
    for (int i = 0; i < 2; i++) {
        const int idx = tid + i * 256;
        const int row = idx >> 2;
        const int c16 = idx & 3;
        const uint32_t doff = sbase + AQ_BYTES + (uint32_t)(row * 80 + c16 * 16);
        const int soff = row * 32 + c16 * 8;
        cpa16(doff, kh + hbase + soff);
        cpa16(doff + 10240, vh + hbase + soff);
    }
    cpcommit();

#pragma unroll
    for (int i = 0; i < 2; i++) {
        const int idx = tid + i * 256;
        const int row = idx >> 2;
        const int c16 = idx & 3;
        ulonglong2 v = *(const ulonglong2*)&qh[hbase + (qt2 * 128 + row) * 32 + c16 * 8];
        const uint32_t off = row * 80 + c16 * 16;
        *(unsigned long long*)(smem + off) = v.x;
        *(unsigned long long*)(smem + off + 8) = v.y;
    }
    __syncthreads();

    uint32_t qfh[2][4];
#pragma unroll
    for (int kc = 0; kc < 2; kc++) {
        const uint32_t ro = (w * 16 + (mat & 1) * 8 + r8) * 80 +
                            (kc * 16 + (mat >> 1) * 8) * 2;
        ldsm4(qfh[kc], sbase + ro);
    }

    float o[4][4];
#pragma unroll
    for (int i = 0; i < 4; i++)
#pragma unroll
        for (int j = 0; j < 4; j++) o[i][j] = 0.0f;
    float l0 = 0.0f, l1 = 0.0f;

    for (int kt = 0; kt < 8; kt++) {
        cpwait<0>();
        __syncthreads();

        if (kt < 7) {
#pragma unroll
            for (int i = 0; i < 2; i++) {
                const int idx = tid + i * 256;
                const int row = idx >> 2;
                const int c16 = idx & 3;
                const uint32_t doff = sbase + AQ_BYTES + ((kt + 1) & 1) * KVBUF +
                                      (uint32_t)(row * 80 + c16 * 16);
                const int soff = ((kt + 1) * 128 + row) * 32 + c16 * 8;
                cpa16(doff, kh + hbase + soff);
                cpa16(doff + 10240, vh + hbase + soff);
            }
        }
        cpcommit();

        const uint32_t kvb = sbase + AQ_BYTES + (kt & 1) * KVBUF;

        float c[16][4];
#pragma unroll
        for (int i = 0; i < 16; i++)
#pragma unroll
            for (int j = 0; j < 4; j++) c[i][j] = 0.0f;

#pragma unroll
        for (int kc = 0; kc < 2; kc++) {
#pragma unroll
            for (int nt2 = 0; nt2 < 8; nt2++) {
                uint32_t br[4];
                ldsm4(br, kvb + (nt2 * 16 + (mat >> 1) * 8 + r8) * 80 +
                          (kc * 16 + (mat & 1) * 8) * 2);
                mma16816(c[2 * nt2], qfh[kc], br);
                mma16816(c[2 * nt2 + 1], qfh[kc], br + 2);
            }
        }

#pragma unroll
        for (int nt = 0; nt < 16; nt++) {
            c[nt][0] = ex2f(c[nt][0]);
            c[nt][1] = ex2f(c[nt][1]);
            c[nt][2] = ex2f(c[nt][2]);
            c[nt][3] = ex2f(c[nt][3]);
            l0 += c[nt][0] + c[nt][1];
            l1 += c[nt][2] + c[nt][3];
        }

#pragma unroll
        for (int ktk = 0; ktk < 8; ktk++) {
            uint32_t ah[4];
            ah[0] = packbf(c[2 * ktk][0], c[2 * ktk][1]);
            ah[1] = packbf(c[2 * ktk][2], c[2 * ktk][3]);
            ah[2] = packbf(c[2 * ktk + 1][0], c[2 * ktk + 1][1]);
            ah[3] = packbf(c[2 * ktk + 1][2], c[2 * ktk + 1][3]);
#pragma unroll
            for (int nh = 0; nh < 2; nh++) {
                uint32_t br[4];
                ldsm4t(br, kvb + 10240 + (ktk * 16 + (mat & 1) * 8 + r8) * 80 +
                           (nh * 16 + (mat >> 1) * 8) * 2);
                mma16816(o[2 * nh], ah, br);
                mma16816(o[2 * nh + 1], ah, br + 2);
            }
        }
    }

    l0 += __shfl_xor_sync(0xffffffffu, l0, 1);
    l0 += __shfl_xor_sync(0xffffffffu, l0, 2);
    l1 += __shfl_xor_sync(0xffffffffu, l1, 1);
    l1 += __shfl_xor_sync(0xffffffffu, l1, 2);

    const float inv0 = 1.0f / l0;
    const float inv1 = 1.0f / l1;
    const int row = b * NS + qt2 * 128 + w * 16 + g;
#pragma unroll
    for (int ot = 0; ot < 4; ot++) {
        const int col = hh * 32 + ot * 8 + tig * 2;
        *(uint32_t*)&outb[(size_t)row * NE + col] =
            packbf(o[ot][0] * inv0, o[ot][1] * inv0);
        *(uint32_t*)&outb[(size_t)(row + 8) * NE + col] =
            packbf(o[ot][2] * inv1, o[ot][3] * inv1);
    }
}

/* ---------------- merged wconv(hi only) + embed ---------------- */
__global__ __launch_bounds__(256) void wconv_embed_kernel(
        const float* __restrict__ ipw, const float* __restrict__ ow,
        const float* __restrict__ w1, const float* __restrict__ w2,
        __nv_bfloat16* __restrict__ wh,
        const float* __restrict__ x, const float* __restrict__ embed_w,
        const float* __restrict__ embed_b, __nv_bfloat16* __restrict__ Cb) {
    if (blockIdx.x < 1152) {
        const int idx = blockIdx.x * 256 + threadIdx.x;
        const int tile = idx >> 14;
        const int e = idx & 16383;
        const int l = tile / 6, t = tile % 6;
        const float* src =
            (t < 3)  ? ipw + (size_t)l * 3 * WTILE + t * WTILE + e :
            (t == 3) ? ow + (size_t)l * WTILE + e :
            (t == 4) ? w1 + (size_t)l * WTILE + e :
                       w2 + (size_t)l * WTILE + e;
        wh[idx] = __float2bfloat16(*src);
        return;
    }
    __shared__ float As[16][64];
    __shared__ float Bs[16][64];
    const int bid = blockIdx.x - 1152;
    const int tid = threadIdx.x;
    const int tx = tid & 15;
    const int ty = tid >> 4;
    const int n0 = (bid & 1) * 64;
    const int m0 = (bid >> 1) * 64;
    const int lrow = tid >> 2;
    const int lk = (tid & 3) * 4;

    float acc[4][4] = {};
    {
        float4 av = *(const float4*)&x[(size_t)(m0 + lrow) * NIN + lk];
        float4 wv = *(const float4*)&embed_w[(size_t)(n0 + lrow) * NIN + lk];
        As[lk + 0][lrow] = av.x; As[lk + 1][lrow] = av.y;
        As[lk + 2][lrow] = av.z; As[lk + 3][lrow] = av.w;
        Bs[lk + 0][lrow] = wv.x; Bs[lk + 1][lrow] = wv.y;
        Bs[lk + 2][lrow] = wv.z; Bs[lk + 3][lrow] = wv.w;
        __syncthreads();
#pragma unroll
        for (int k = 0; k < 16; k++) {
            float4 a4 = *(const float4*)&As[k][ty * 4];
            float4 b4 = *(const float4*)&Bs[k][tx * 4];
            float ar[4] = {a4.x, a4.y, a4.z, a4.w};
            float br[4] = {b4.x, b4.y, b4.z, b4.w};
#pragma unroll
            for (int i = 0; i < 4; i++)
#pragma unroll
                for (int j = 0; j < 4; j++) acc[i][j] += ar[i] * br[j];
        }
    }
#pragma unroll
    for (int i = 0; i < 4; i++) {
        const int m = m0 + ty * 4 + i;
#pragma unroll
        for (int j = 0; j < 4; j += 2) {
            const int n = n0 + tx * 4 + j;
            *(uint32_t*)&Cb[(size_t)m * NE + n] =
                packbf(fmaxf(acc[i][j] + embed_b[n], 0.0f),
                       fmaxf(acc[i][j + 1] + embed_b[n + 1], 0.0f));
        }
    }
}

/* ---------------- pool stage 1 (bf16 in) ---------------- */
__global__ __launch_bounds__(128) void pool1_kernel(const __nv_bfloat16* __restrict__ h,
                                                    const float* __restrict__ mask,
                                                    float* __restrict__ part) {
    const int b = blockIdx.y;
    const int j = blockIdx.x;
    const int e = threadIdx.x;
    float s = 0.0f;
#pragma unroll 8
    for (int k = 0; k < 128; k++) {
        const int sx = j * 128 + k;
        s += bf2f(h[(size_t)(b * NS + sx) * NE + e]) * mask[b * NS + sx];
    }
    part[(size_t)(b * 8 + j) * NE + e] = s;
}

/* ---------------- fused classifier ---------------- */
__global__ __launch_bounds__(256) void cls_kernel(
        const float* __restrict__ part,
        const float* __restrict__ cw1, const float* __restrict__ cb1,
        const float* __restrict__ cw2, const float* __restrict__ cb2,
        const float* __restrict__ cw3, const float* __restrict__ cb3,
        const float* __restrict__ cw4, const float* __restrict__ cb4,
        float* __restrict__ out) {
    __shared__ float pooled[128];
    __shared__ float za[256];
    __shared__ float zb[256];
    __shared__ float ws[8];
    const int b = blockIdx.x;
    const int t = threadIdx.x;

    if (t < 128) {
        float s = 0.0f;
#pragma unroll
        for (int j = 0; j < 8; j++) s += part[(size_t)(b * 8 + j) * NE + t];
        pooled[t] = s;
    }
    __syncthreads();

    {
        float s = cb1[t];
        const float* wr = &cw1[t * 128];
#pragma unroll 8
        for (int k = 0; k < 128; k++) s += pooled[k] * wr[k];
        za[t] = fmaxf(s, 0.0f);
    }
    __syncthreads();
    {
        float s = cb2[t];
        const float* wr = &cw2[t * 256];
#pragma unroll 8
        for (int k = 0; k < 256; k++) s += za[k] * wr[k];
        zb[t] = fmaxf(s, 0.0f);
    }
    __syncthreads();
    {
        float s = cb3[t];
        const float* wr = &cw3[t * 256];
#pragma unroll 8
        for (int k = 0; k < 256; k++) s += zb[k] * wr[k];
        za[t] = fmaxf(s, 0.0f);
    }
    __syncthreads();
    {
        float p = za[t] * cw4[t];
#pragma unroll
        for (int ofs = 16; ofs > 0; ofs >>= 1)
            p += __shfl_xor_sync(0xffffffffu, p, ofs);
        if ((t & 31) == 0) ws[t >> 5] = p;
        __syncthreads();
        if (t == 0) {
            float tot = cb4[0];
#pragma unroll
            for (int j = 0; j < 8; j++) tot += ws[j];
            out[b] = 1.0f / (1.0f + __expf(-tot));
        }
    }
}

extern "C" void kernel_launch(void* const* d_in, const int* in_sizes, int n_in,
                              void* d_out, int out_size) {
    const float* x       = (const float*)d_in[0];
    const float* mask    = (const float*)d_in[1];
    const float* embed_w = (const float*)d_in[2];
    const float* embed_b = (const float*)d_in[3];
    const float* ipw     = (const float*)d_in[4];
    const float* ipb     = (const float*)d_in[5];
    const float* ow      = (const float*)d_in[6];
    const float* ob      = (const float*)d_in[7];
    const float* ln1g    = (const float*)d_in[8];
    const float* ln1b    = (const float*)d_in[9];
    const float* ln2g    = (const float*)d_in[10];
    const float* ln2b    = (const float*)d_in[11];
    const float* w1      = (const float*)d_in[12];
    const float* fb1     = (const float*)d_in[13];
    const float* w2      = (const float*)d_in[14];
    const float* fb2     = (const float*)d_in[15];
    const float* cw1     = (const float*)d_in[16];
    const float* cb1     = (const float*)d_in[17];
    const float* cw2     = (const float*)d_in[18];
    const float* cb2     = (const float*)d_in[19];
    const float* cw3     = (const float*)d_in[20];
    const float* cb3     = (const float*)d_in[21];
    const float* cw4     = (const float*)d_in[22];
    const float* cb4     = (const float*)d_in[23];

    float *poolp;
    __nv_bfloat16 *hbf, *attnbf, *qh, *kh, *vh, *wh;
    cudaGetSymbolAddress((void**)&poolp, g_poolp);
    cudaGetSymbolAddress((void**)&hbf, g_hbf);
    cudaGetSymbolAddress((void**)&attnbf, g_attnbf);
    cudaGetSymbolAddress((void**)&qh, g_qh);
    cudaGetSymbolAddress((void**)&kh, g_kh);
    cudaGetSymbolAddress((void**)&vh, g_vh);
    cudaGetSymbolAddress((void**)&wh, g_wh);

    cudaFuncSetAttribute(gemm_qkv1_kernel,
                         cudaFuncAttributeMaxDynamicSharedMemorySize, SMEM_QKV);
    cudaFuncSetAttribute(gemm_fused3_kernel,
                         cudaFuncAttributeMaxDynamicSharedMemorySize, SMEM_MMA);
    cudaFuncSetAttribute(attn_mma_kernel,
                         cudaFuncAttributeMaxDynamicSharedMemorySize, ATT_SMEM);

    wconv_embed_kernel<<<2176, 256>>>(ipw, ow, w1, w2, wh,
                                      x, embed_w, embed_b, hbf);

    for (int i = 0; i < 3; i++) {
        const __nv_bfloat16* whb = wh + (size_t)i * 6 * WTILE;
        const float* ipb_i = ipb + (size_t)i * 3 * NE;
        const float* ob_i  = ob  + (size_t)i * NE;
        const float* l1g   = ln1g + (size_t)i * NE;
        const float* l1b   = ln1b + (size_t)i * NE;
        const float* l2g   = ln2g + (size_t)i * NE;
        const float* l2b   = ln2b + (size_t)i * NE;
        const float* fb1_i = fb1 + (size_t)i * NE;
        const float* fb2_i = fb2 + (size_t)i * NE;

        gemm_qkv1_kernel<<<dim3(3, 256), 256, SMEM_QKV>>>(hbf, whb, ipb_i,
                                                          qh, kh, vh);
        attn_mma_kernel<<<1024, 256, ATT_SMEM>>>(qh, kh, vh, attnbf);
        gemm_fused3_kernel<<<dim3(1, 256), 256, SMEM_MMA>>>(
            attnbf, whb, ob_i, fb1_i, fb2_i, l1g, l1b, l2g, l2b, hbf);
    }

    pool1_kernel<<<dim3(8, NB), 128>>>(hbf, mask, poolp);
    cls_kernel<<<NB, 256>>>(poolp, cw1, cb1, cw2, cb2, cw3, cb3, cw4, cb4,
                            (float*)d_out);
}

// round 16
// speedup vs baseline: 1.0215x; 1.0215x over previous
#include <cuda_runtime.h>
#include <cuda_bf16.h>
#include <math.h>
#include <stdint.h>

#define NB 32
#define NS 1024
#define NIN 16
#define NE 128
#define NHID 256
#define NDH 32
#define TOK (NB * NS)          /* 32768 */
#define EPSV 1e-5f
#define HSTRIDE (NS * NDH)     /* 32768 elems per (b,head) */

/* ---------------- scratch ---------------- */
__device__ float g_poolp[NB * 8 * NE];
__device__ __nv_bfloat16 g_hbf[TOK * NE];
__device__ __nv_bfloat16 g_attnbf[TOK * NE];
__device__ __nv_bfloat16 g_qh[NB * 4 * HSTRIDE];
__device__ __nv_bfloat16 g_kh[NB * 4 * HSTRIDE];
__device__ __nv_bfloat16 g_vh[NB * 4 * HSTRIDE];
#define WTILE (128 * 128)
__device__ __nv_bfloat16 g_wh[3 * 6 * WTILE];   /* bf16 weights */

/* ================= common helpers ================= */
__device__ __forceinline__ uint32_t smem_u32(const void* p) {
    uint32_t a;
    asm("{ .reg .u64 t; cvta.to.shared.u64 t, %1; cvt.u32.u64 %0, t; }" : "=r"(a) : "l"(p));
    return a;
}
__device__ __forceinline__ void ldsm4(uint32_t* r, uint32_t addr) {
    asm volatile("ldmatrix.sync.aligned.m8n8.x4.shared.b16 {%0,%1,%2,%3}, [%4];"
                 : "=r"(r[0]), "=r"(r[1]), "=r"(r[2]), "=r"(r[3]) : "r"(addr));
}
__device__ __forceinline__ void ldsm4t(uint32_t* r, uint32_t addr) {
    asm volatile("ldmatrix.sync.aligned.m8n8.x4.trans.shared.b16 {%0,%1,%2,%3}, [%4];"
                 : "=r"(r[0]), "=r"(r[1]), "=r"(r[2]), "=r"(r[3]) : "r"(addr));
}
__device__ __forceinline__ void mma16816(float* c, const uint32_t* a, const uint32_t* b) {
    asm volatile(
        "mma.sync.aligned.m16n8k16.row.col.f32.bf16.bf16.f32 "
        "{%0,%1,%2,%3}, {%4,%5,%6,%7}, {%8,%9}, {%0,%1,%2,%3};"
        : "+f"(c[0]), "+f"(c[1]), "+f"(c[2]), "+f"(c[3])
        : "r"(a[0]), "r"(a[1]), "r"(a[2]), "r"(a[3]), "r"(b[0]), "r"(b[1]));
}
__device__ __forceinline__ float ex2f(float x) {
    float r; asm("ex2.approx.f32 %0, %1;" : "=f"(r) : "f"(x)); return r;
}
__device__ __forceinline__ uint32_t packbf(float lo, float hi) {
    uint32_t r;
    asm("cvt.rn.bf16x2.f32 %0, %1, %2;" : "=r"(r) : "f"(hi), "f"(lo));
    return r;
}
__device__ __forceinline__ float bf2f(__nv_bfloat16 v) { return __bfloat162float(v); }
__device__ __forceinline__ void cpa16(uint32_t dst, const void* src) {
    asm volatile("cp.async.cg.shared.global [%0], [%1], 16;" :: "r"(dst), "l"(src));
}
__device__ __forceinline__ void cpcommit() { asm volatile("cp.async.commit_group;"); }
template <int N>
__device__ __forceinline__ void cpwait() {
    asm volatile("cp.async.wait_group %0;" :: "n"(N) : "memory");
}

/* ================= GEMM building blocks ================= */
#define TROW 136
#define TILE_BYTES (128 * TROW * 2)   /* 34816 */
#define SMEM_MMA (3 * TILE_BYTES)     /* A + 2 W slots (double-buffer) */

__device__ __forceinline__ void load_A(const __nv_bfloat16* __restrict__ A,
                                       uint32_t sbase, int tid) {
#pragma unroll
    for (int i = 0; i < 8; i++) {
        const int idx = tid + i * 256;
        const int row = idx >> 4;
        const int c16 = idx & 15;
        cpa16(sbase + (uint32_t)(row * 272 + c16 * 16), A + row * 128 + c16 * 8);
    }
}
__device__ __forceinline__ void load_Wslot(const __nv_bfloat16* __restrict__ W,
                                           uint32_t slotbase, int tid) {
#pragma unroll
    for (int i = 0; i < 8; i++) {
        const int idx = tid + i * 256;
        const int row = idx >> 4;
        const int c16 = idx & 15;
        cpa16(slotbase + (uint32_t)(row * 272 + c16 * 16), W + row * 128 + c16 * 8);
    }
    cpcommit();
}
/* single K-pass (bf16 W): interleaved ldsm->2xMMA */
__device__ __forceinline__ void mma_pass(uint32_t sbase, uint32_t wbase,
                                         int tid, float acc[16][4]) {
    const int w = tid >> 5;
    const int lane = tid & 31;
    const int mat = lane >> 3;
    const int r8 = lane & 7;
#pragma unroll
    for (int kc = 0; kc < 8; kc++) {
        const int k0 = kc * 16;
        uint32_t afr[4];
        ldsm4(afr, sbase + ((w * 16 + (mat & 1) * 8 + r8) * TROW +
                            k0 + (mat >> 1) * 8) * 2);
#pragma unroll
        for (int nt2 = 0; nt2 < 8; nt2++) {
            uint32_t br[4];
            ldsm4(br, wbase + ((nt2 * 16 + (mat >> 1) * 8 + r8) * TROW +
                               k0 + (mat & 1) * 8) * 2);
            mma16816(acc[2 * nt2], afr, br);
            mma16816(acc[2 * nt2 + 1], afr, br + 2);
        }
    }
}

/* ---------- fused qkv GEMM (double-buffered W) — R14 validated ---------- */
__global__ __launch_bounds__(256, 2) void gemm_qkv3_kernel(
        const __nv_bfloat16* __restrict__ A, const __nv_bfloat16* __restrict__ whb,
        const float* __restrict__ bias,
        __nv_bfloat16* __restrict__ qh, __nv_bfloat16* __restrict__ kh,
        __nv_bfloat16* __restrict__ vh) {
    extern __shared__ char smem[];
    const uint32_t sbase = smem_u32(smem);
    const int tid = threadIdx.x;
    const int m0 = blockIdx.y * 128;
    const int lane = tid & 31;
    const int w = tid >> 5;
    const int g = lane >> 2;
    const int tig = lane & 3;
    const int tok0 = m0 + w * 16 + g;
    const float qscale = 1.4426950408889634f * 0.17677669529663687f;

    load_A(A + (size_t)m0 * 128, sbase, tid);
    load_Wslot(whb, sbase + TILE_BYTES, tid);               /* G1 = A + W0 */
    load_Wslot(whb + WTILE, sbase + 2 * TILE_BYTES, tid);   /* G2 = W1 */
    cpwait<1>();                                            /* A + W0 ready */
    __syncthreads();

#pragma unroll
    for (int x = 0; x < 3; x++) {
        float acc[16][4];
#pragma unroll
        for (int i = 0; i < 16; i++)
#pragma unroll
            for (int j = 0; j < 4; j++) acc[i][j] = 0.0f;

        mma_pass(sbase, sbase + TILE_BYTES * (1 + (x & 1)), tid, acc);
        __syncthreads();
        if (x == 0)
            load_Wslot(whb + 2 * WTILE, sbase + TILE_BYTES, tid);   /* G3 */

        __nv_bfloat16* dhi = (x == 0) ? qh : (x == 1) ? kh : vh;
#pragma unroll
        for (int nt = 0; nt < 16; nt++) {
            const int cc = nt * 8 + tig * 2;
            float2 b01 = *(const float2*)&bias[x * 128 + cc];
            float v00 = acc[nt][0] + b01.x, v01 = acc[nt][1] + b01.y;
            float v10 = acc[nt][2] + b01.x, v11 = acc[nt][3] + b01.y;
            if (x == 0) { v00 *= qscale; v01 *= qscale; v10 *= qscale; v11 *= qscale; }
            const int hh = cc >> 5;
            const int d = cc & 31;
            const size_t i0 = ((size_t)((tok0 >> 10) * 4 + hh) << 15) +
                              (tok0 & 1023) * 32 + d;
            const size_t i1 = i0 + 8 * 32;
            *(uint32_t*)&dhi[i0] = packbf(v00, v01);
            *(uint32_t*)&dhi[i1] = packbf(v10, v11);
        }

        if (x == 0) { cpwait<1>(); __syncthreads(); }
        if (x == 1) { cpwait<0>(); __syncthreads(); }
    }
}

/* ---------- fused layer tail (R14 validated) ---------- */
__global__ __launch_bounds__(256, 2) void gemm_fused3_kernel(
        const __nv_bfloat16* __restrict__ attnA, const __nv_bfloat16* __restrict__ whb,
        const float* __restrict__ ob,
        const float* __restrict__ fb1, const float* __restrict__ fb2,
        const float* __restrict__ l1g, const float* __restrict__ l1b,
        const float* __restrict__ l2g, const float* __restrict__ l2b,
        __nv_bfloat16* __restrict__ hio) {
    extern __shared__ char smem[];
    const uint32_t sbase = smem_u32(smem);
    const int tid = threadIdx.x;
    const int m0 = blockIdx.y * 128;
    const int lane = tid & 31;
    const int w = tid >> 5;
    const int g = lane >> 2;
    const int tig = lane & 3;
    const int row0 = m0 + w * 16 + g;
    const int row1 = row0 + 8;
    const int srow0 = w * 16 + g;
    const int srow1 = srow0 + 8;

    float acc[16][4];
    uint32_t h2p[32];

    load_A(attnA + (size_t)m0 * 128, sbase, tid);
    load_Wslot(whb + 3 * WTILE, sbase + TILE_BYTES, tid);
    load_Wslot(whb + 4 * WTILE, sbase + 2 * TILE_BYTES, tid);
    cpwait<1>();
    __syncthreads();

    /* ===== stage 1: out-proj + resid + LN ===== */
#pragma unroll
    for (int i = 0; i < 16; i++)
#pragma unroll
        for (int j = 0; j < 4; j++) acc[i][j] = 0.0f;
    mma_pass(sbase, sbase + TILE_BYTES, tid, acc);
    __syncthreads();
    load_Wslot(whb + 5 * WTILE, sbase + TILE_BYTES, tid);

    {
        float s0 = 0.0f, s1 = 0.0f;
#pragma unroll
        for (int nt = 0; nt < 16; nt++) {
            const int cc = nt * 8 + tig * 2;
            float2 b01 = *(const float2*)&ob[cc];
            __nv_bfloat162 r0 = *(const __nv_bfloat162*)&hio[(size_t)row0 * NE + cc];
            __nv_bfloat162 r1 = *(const __nv_bfloat162*)&hio[(size_t)row1 * NE + cc];
            acc[nt][0] += b01.x + bf2f(r0.x); acc[nt][1] += b01.y + bf2f(r0.y);
            acc[nt][2] += b01.x + bf2f(r1.x); acc[nt][3] += b01.y + bf2f(r1.y);
            s0 += acc[nt][0] + acc[nt][1];
            s1 += acc[nt][2] + acc[nt][3];
        }
        s0 += __shfl_xor_sync(0xffffffffu, s0, 1);
        s0 += __shfl_xor_sync(0xffffffffu, s0, 2);
        s1 += __shfl_xor_sync(0xffffffffu, s1, 1);
        s1 += __shfl_xor_sync(0xffffffffu, s1, 2);
        const float mean0 = s0 * (1.0f / NE), mean1 = s1 * (1.0f / NE);
        float q0 = 0.0f, q1 = 0.0f;
#pragma unroll
        for (int nt = 0; nt < 16; nt++) {
            const float d0 = acc[nt][0] - mean0, d1 = acc[nt][1] - mean0;
            const float d2 = acc[nt][2] - mean1, d3 = acc[nt][3] - mean1;
            q0 += d0 * d0 + d1 * d1;
            q1 += d2 * d2 + d3 * d3;
        }
        q0 += __shfl_xor_sync(0xffffffffu, q0, 1);
        q0 += __shfl_xor_sync(0xffffffffu, q0, 2);
        q1 += __shfl_xor_sync(0xffffffffu, q1, 1);
        q1 += __shfl_xor_sync(0xffffffffu, q1, 2);
        const float rstd0 = rsqrtf(q0 * (1.0f / NE) + EPSV);
        const float rstd1 = rsqrtf(q1 * (1.0f / NE) + EPSV);
#pragma unroll
        for (int nt = 0; nt < 16; nt++) {
            const int cc = nt * 8 + tig * 2;
            float2 gg = *(const float2*)&l1g[cc];
            float2 bb = *(const float2*)&l1b[cc];
            h2p[2 * nt] = packbf((acc[nt][0] - mean0) * rstd0 * gg.x + bb.x,
                                 (acc[nt][1] - mean0) * rstd0 * gg.y + bb.y);
            h2p[2 * nt + 1] = packbf((acc[nt][2] - mean1) * rstd1 * gg.x + bb.x,
                                     (acc[nt][3] - mean1) * rstd1 * gg.y + bb.y);
            *(uint32_t*)(smem + (srow0 * TROW + cc) * 2) = h2p[2 * nt];
            *(uint32_t*)(smem + (srow1 * TROW + cc) * 2) = h2p[2 * nt + 1];
        }
    }
    __syncthreads();
    cpwait<1>();
    __syncthreads();

    /* ===== stage 2: ffn1 + relu ===== */
#pragma unroll
    for (int i = 0; i < 16; i++)
#pragma unroll
        for (int j = 0; j < 4; j++) acc[i][j] = 0.0f;
    mma_pass(sbase, sbase + 2 * TILE_BYTES, tid, acc);
    __syncthreads();

#pragma unroll
    for (int nt = 0; nt < 16; nt++) {
        const int cc = nt * 8 + tig * 2;
        float2 b01 = *(const float2*)&fb1[cc];
        *(uint32_t*)(smem + (srow0 * TROW + cc) * 2) =
            packbf(fmaxf(acc[nt][0] + b01.x, 0.0f), fmaxf(acc[nt][1] + b01.y, 0.0f));
        *(uint32_t*)(smem + (srow1 * TROW + cc) * 2) =
            packbf(fmaxf(acc[nt][2] + b01.x, 0.0f), fmaxf(acc[nt][3] + b01.y, 0.0f));
    }
    __syncthreads();
    cpwait<0>();
    __syncthreads();

    /* ===== stage 3: ffn2 + resid(h2) + LN -> hio ===== */
#pragma unroll
    for (int i = 0; i < 16; i++)
#pragma unroll
        for (int j = 0; j < 4; j++) acc[i][j] = 0.0f;
    mma_pass(sbase, sbase + TILE_BYTES, tid, acc);

    {
        float s0 = 0.0f, s1 = 0.0f;
#pragma unroll
        for (int nt = 0; nt < 16; nt++) {
            const int cc = nt * 8 + tig * 2;
            float2 b01 = *(const float2*)&fb2[cc];
            const __nv_bfloat162 r0 = *(const __nv_bfloat162*)&h2p[2 * nt];
            const __nv_bfloat162 r1 = *(const __nv_bfloat162*)&h2p[2 * nt + 1];
            acc[nt][0] += b01.x + bf2f(r0.x); acc[nt][1] += b01.y + bf2f(r0.y);
            acc[nt][2] += b01.x + bf2f(r1.x); acc[nt][3] += b01.y + bf2f(r1.y);
            s0 += acc[nt][0] + acc[nt][1];
            s1 += acc[nt][2] + acc[nt][3];
        }
        s0 += __shfl_xor_sync(0xffffffffu, s0, 1);
        s0 += __shfl_xor_sync(0xffffffffu, s0, 2);
        s1 += __shfl_xor_sync(0xffffffffu, s1, 1);
        s1 += __shfl_xor_sync(0xffffffffu, s1, 2);
        const float mean0 = s0 * (1.0f / NE), mean1 = s1 * (1.0f / NE);
        float q0 = 0.0f, q1 = 0.0f;
#pragma unroll
        for (int nt = 0; nt < 16; nt++) {
            const float d0 = acc[nt][0] - mean0, d1 = acc[nt][1] - mean0;
            const float d2 = acc[nt][2] - mean1, d3 = acc[nt][3] - mean1;
            q0 += d0 * d0 + d1 * d1;
            q1 += d2 * d2 + d3 * d3;
        }
        q0 += __shfl_xor_sync(0xffffffffu, q0, 1);
        q0 += __shfl_xor_sync(0xffffffffu, q0, 2);
        q1 += __shfl_xor_sync(0xffffffffu, q1, 1);
        q1 += __shfl_xor_sync(0xffffffffu, q1, 2);
        const float rstd0 = rsqrtf(q0 * (1.0f / NE) + EPSV);
        const float rstd1 = rsqrtf(q1 * (1.0f / NE) + EPSV);
#pragma unroll
        for (int nt = 0; nt < 16; nt++) {
            const int cc = nt * 8 + tig * 2;
            float2 gg = *(const float2*)&l2g[cc];
            float2 bb = *(const float2*)&l2b[cc];
            *(uint32_t*)&hio[(size_t)row0 * NE + cc] =
                packbf((acc[nt][0] - mean0) * rstd0 * gg.x + bb.x,
                       (acc[nt][1] - mean0) * rstd0 * gg.y + bb.y);
            *(uint32_t*)&hio[(size_t)row1 * NE + cc] =
                packbf((acc[nt][2] - mean1) * rstd1 * gg.x + bb.x,
                       (acc[nt][3] - mean1) * rstd1 * gg.y + bb.y);
        }
    }
}

/* ================= MMA flash attention: 2 q-tiles/CTA, interleaved
   softmax+PV per ktk (same fp ops & order -> bit-identical to R14) ========= */
#define AQ_BYTES 10240                  /* 128 rows x 80B */
#define KVBUF 20480
#define ATT_SMEM (AQ_BYTES + 2 * KVBUF) /* 51200, dynamic */

__global__ __launch_bounds__(256, 2) void attn_mma_kernel(
        const __nv_bfloat16* __restrict__ qh, const __nv_bfloat16* __restrict__ kh,
        const __nv_bfloat16* __restrict__ vh, __nv_bfloat16* __restrict__ outb) {
    extern __shared__ char smem[];
    const uint32_t sbase = smem_u32(smem);

    const int blk = blockIdx.x;        /* b(32) x hh(4) x qt2(8) */
    const int qt2 = blk & 7;
    const int hh = (blk >> 3) & 3;
    const int b = blk >> 5;
    const int tid = threadIdx.x;
    const int w = tid >> 5;
    const int lane = tid & 31;
    const int mat = lane >> 3;
    const int r8 = lane & 7;
    const int g = lane >> 2;
    const int tig = lane & 3;

    const size_t hbase = (size_t)(b * 4 + hh) * HSTRIDE;

#pragma unroll
    for (int i = 0; i < 2; i++) {
        const int idx = tid + i * 256;
        const int row = idx >> 2;
        const int c16 = idx & 3;
        const uint32_t doff = sbase + AQ_BYTES + (uint32_t)(row * 80 + c16 * 16);
        const int soff = row * 32 + c16 * 8;
        cpa16(doff, kh + hbase + soff);
        cpa16(doff + 10240, vh + hbase + soff);
    }
    cpcommit();

#pragma unroll
    for (int i = 0; i < 2; i++) {
        const int idx = tid + i * 256;
        const int row = idx >> 2;
        const int c16 = idx & 3;
        ulonglong2 v = *(const ulonglong2*)&qh[hbase + (qt2 * 128 + row) * 32 + c16 * 8];
        const uint32_t off = row * 80 + c16 * 16;
        *(unsigned long long*)(smem + off) = v.x;
        *(unsigned long long*)(smem + off + 8) = v.y;
    }
    __syncthreads();

    uint32_t qfh[2][4];
#pragma unroll
    for (int kc = 0; kc < 2; kc++) {
        const uint32_t ro = (w * 16 + (mat & 1) * 8 + r8) * 80 +
                            (kc * 16 + (mat >> 1) * 8) * 2;
        ldsm4(qfh[kc], sbase + ro);
    }

    float o[4][4];
#pragma unroll
    for (int i = 0; i < 4; i++)
#pragma unroll
        for (int j = 0; j < 4; j++) o[i][j] = 0.0f;
    float l0 = 0.0f, l1 = 0.0f;

    for (int kt = 0; kt < 8; kt++) {
        cpwait<0>();
        __syncthreads();

        if (kt < 7) {
#pragma unroll
            for (int i = 0; i < 2; i++) {
                const int idx = tid + i * 256;
                const int row = idx >> 2;
                const int c16 = idx & 3;
                const uint32_t doff = sbase + AQ_BYTES + ((kt + 1) & 1) * KVBUF +
                                      (uint32_t)(row * 80 + c16 * 16);
                const int soff = ((kt + 1) * 128 + row) * 32 + c16 * 8;
                cpa16(doff, kh + hbase + soff);
                cpa16(doff + 10240, vh + hbase + soff);
            }
        }
        cpcommit();

        const uint32_t kvb = sbase + AQ_BYTES + (kt & 1) * KVBUF;

        float c[16][4];
#pragma unroll
        for (int i = 0; i < 16; i++)
#pragma unroll
            for (int j = 0; j < 4; j++) c[i][j] = 0.0f;

#pragma unroll
        for (int kc = 0; kc < 2; kc++) {
#pragma unroll
            for (int nt2 = 0; nt2 < 8; nt2++) {
                uint32_t br[4];
                ldsm4(br, kvb + (nt2 * 16 + (mat >> 1) * 8 + r8) * 80 +
                          (kc * 16 + (mat & 1) * 8) * 2);
                mma16816(c[2 * nt2], qfh[kc], br);
                mma16816(c[2 * nt2 + 1], qfh[kc], br + 2);
            }
        }

        /* interleaved softmax + PV: per ktk, ex2(8) -> l-adds -> pack -> 4 MMA.
           Same fp ops in the same order as the phase-separated version. */
#pragma unroll
        for (int ktk = 0; ktk < 8; ktk++) {
            float* c0 = c[2 * ktk];
            float* c1 = c[2 * ktk + 1];
            c0[0] = ex2f(c0[0]); c0[1] = ex2f(c0[1]);
            c0[2] = ex2f(c0[2]); c0[3] = ex2f(c0[3]);
            l0 += c0[0] + c0[1];
            l1 += c0[2] + c0[3];
            c1[0] = ex2f(c1[0]); c1[1] = ex2f(c1[1]);
            c1[2] = ex2f(c1[2]); c1[3] = ex2f(c1[3]);
            l0 += c1[0] + c1[1];
            l1 += c1[2] + c1[3];

            uint32_t ah[4];
            ah[0] = packbf(c0[0], c0[1]);
            ah[1] = packbf(c0[2], c0[3]);
            ah[2] = packbf(c1[0], c1[1]);
            ah[3] = packbf(c1[2], c1[3]);
#pragma unroll
            for (int nh = 0; nh < 2; nh++) {
                uint32_t br[4];
                ldsm4t(br, kvb + 10240 + (ktk * 16 + (mat & 1) * 8 + r8) * 80 +
                           (nh * 16 + (mat >> 1) * 8) * 2);
                mma16816(o[2 * nh], ah, br);
                mma16816(o[2 * nh + 1], ah, br + 2);
            }
        }
    }

    l0 += __shfl_xor_sync(0xffffffffu, l0, 1);
    l0 += __shfl_xor_sync(0xffffffffu, l0, 2);
    l1 += __shfl_xor_sync(0xffffffffu, l1, 1);
    l1 += __shfl_xor_sync(0xffffffffu, l1, 2);

    const float inv0 = 1.0f / l0;
    const float inv1 = 1.0f / l1;
    const int row = b * NS + qt2 * 128 + w * 16 + g;
#pragma unroll
    for (int ot = 0; ot < 4; ot++) {
        const int col = hh * 32 + ot * 8 + tig * 2;
        *(uint32_t*)&outb[(size_t)row * NE + col] =
            packbf(o[ot][0] * inv0, o[ot][1] * inv0);
        *(uint32_t*)&outb[(size_t)(row + 8) * NE + col] =
            packbf(o[ot][2] * inv1, o[ot][3] * inv1);
    }
}

/* ---------------- merged wconv(hi only) + embed ---------------- */
__global__ __launch_bounds__(256) void wconv_embed_kernel(
        const float* __restrict__ ipw, const float* __restrict__ ow,
        const float* __restrict__ w1, const float* __restrict__ w2,
        __nv_bfloat16* __restrict__ wh,
        const float* __restrict__ x, const float* __restrict__ embed_w,
        const float* __restrict__ embed_b, __nv_bfloat16* __restrict__ Cb) {
    if (blockIdx.x < 1152) {
        const int idx = blockIdx.x * 256 + threadIdx.x;
        const int tile = idx >> 14;
        const int e = idx & 16383;
        const int l = tile / 6, t = tile % 6;
        const float* src =
            (t < 3)  ? ipw + (size_t)l * 3 * WTILE + t * WTILE + e :
            (t == 3) ? ow + (size_t)l * WTILE + e :
            (t == 4) ? w1 + (size_t)l * WTILE + e :
                       w2 + (size_t)l * WTILE + e;
        wh[idx] = __float2bfloat16(*src);
        return;
    }
    __shared__ float As[16][64];
    __shared__ float Bs[16][64];
    const int bid = blockIdx.x - 1152;
    const int tid = threadIdx.x;
    const int tx = tid & 15;
    const int ty = tid >> 4;
    const int n0 = (bid & 1) * 64;
    const int m0 = (bid >> 1) * 64;
    const int lrow = tid >> 2;
    const int lk = (tid & 3) * 4;

    float acc[4][4] = {};
    {
        float4 av = *(const float4*)&x[(size_t)(m0 + lrow) * NIN + lk];
        float4 wv = *(const float4*)&embed_w[(size_t)(n0 + lrow) * NIN + lk];
        As[lk + 0][lrow] = av.x; As[lk + 1][lrow] = av.y;
        As[lk + 2][lrow] = av.z; As[lk + 3][lrow] = av.w;
        Bs[lk + 0][lrow] = wv.x; Bs[lk + 1][lrow] = wv.y;
        Bs[lk + 2][lrow] = wv.z; Bs[lk + 3][lrow] = wv.w;
        __syncthreads();
#pragma unroll
        for (int k = 0; k < 16; k++) {
            float4 a4 = *(const float4*)&As[k][ty * 4];
            float4 b4 = *(const float4*)&Bs[k][tx * 4];
            float ar[4] = {a4.x, a4.y, a4.z, a4.w};
            float br[4] = {b4.x, b4.y, b4.z, b4.w};
#pragma unroll
            for (int i = 0; i < 4; i++)
#pragma unroll
                for (int j = 0; j < 4; j++) acc[i][j] += ar[i] * br[j];
        }
    }
#pragma unroll
    for (int i = 0; i < 4; i++) {
        const int m = m0 + ty * 4 + i;
#pragma unroll
        for (int j = 0; j < 4; j += 2) {
            const int n = n0 + tx * 4 + j;
            *(uint32_t*)&Cb[(size_t)m * NE + n] =
                packbf(fmaxf(acc[i][j] + embed_b[n], 0.0f),
                       fmaxf(acc[i][j + 1] + embed_b[n + 1], 0.0f));
        }
    }
}

/* ---------------- pool stage 1 (bf16 in) ---------------- */
__global__ __launch_bounds__(128) void pool1_kernel(const __nv_bfloat16* __restrict__ h,
                                                    const float* __restrict__ mask,
                                                    float* __restrict__ part) {
    const int b = blockIdx.y;
    const int j = blockIdx.x;
    const int e = threadIdx.x;
    float s = 0.0f;
#pragma unroll 8
    for (int k = 0; k < 128; k++) {
        const int sx = j * 128 + k;
        s += bf2f(h[(size_t)(b * NS + sx) * NE + e]) * mask[b * NS + sx];
    }
    part[(size_t)(b * 8 + j) * NE + e] = s;
}

/* ---------------- fused classifier ---------------- */
__global__ __launch_bounds__(256) void cls_kernel(
        const float* __restrict__ part,
        const float* __restrict__ cw1, const float* __restrict__ cb1,
        const float* __restrict__ cw2, const float* __restrict__ cb2,
        const float* __restrict__ cw3, const float* __restrict__ cb3,
        const float* __restrict__ cw4, const float* __restrict__ cb4,
        float* __restrict__ out) {
    __shared__ float pooled[128];
    __shared__ float za[256];
    __shared__ float zb[256];
    __shared__ float ws[8];
    const int b = blockIdx.x;
    const int t = threadIdx.x;

    if (t < 128) {
        float s = 0.0f;
#pragma unroll
        for (int j = 0; j < 8; j++) s += part[(size_t)(b * 8 + j) * NE + t];
        pooled[t] = s;
    }
    __syncthreads();

    {
        float s = cb1[t];
        const float* wr = &cw1[t * 128];
#pragma unroll 8
        for (int k = 0; k < 128; k++) s += pooled[k] * wr[k];
        za[t] = fmaxf(s, 0.0f);
    }
    __syncthreads();
    {
        float s = cb2[t];
        const float* wr = &cw2[t * 256];
#pragma unroll 8
        for (int k = 0; k < 256; k++) s += za[k] * wr[k];
        zb[t] = fmaxf(s, 0.0f);
    }
    __syncthreads();
    {
        float s = cb3[t];
        const float* wr = &cw3[t * 256];
#pragma unroll 8
        for (int k = 0; k < 256; k++) s += zb[k] * wr[k];
        za[t] = fmaxf(s, 0.0f);
    }
    __syncthreads();
    {
        float p = za[t] * cw4[t];
#pragma unroll
        for (int ofs = 16; ofs > 0; ofs >>= 1)
            p += __shfl_xor_sync(0xffffffffu, p, ofs);
        if ((t & 31) == 0) ws[t >> 5] = p;
        __syncthreads();
        if (t == 0) {
            float tot = cb4[0];
#pragma unroll
            for (int j = 0; j < 8; j++) tot += ws[j];
            out[b] = 1.0f / (1.0f + __expf(-tot));
        }
    }
}

extern "C" void kernel_launch(void* const* d_in, const int* in_sizes, int n_in,
                              void* d_out, int out_size) {
    const float* x       = (const float*)d_in[0];
    const float* mask    = (const float*)d_in[1];
    const float* embed_w = (const float*)d_in[2];
    const float* embed_b = (const float*)d_in[3];
    const float* ipw     = (const float*)d_in[4];
    const float* ipb     = (const float*)d_in[5];
    const float* ow      = (const float*)d_in[6];
    const float* ob      = (const float*)d_in[7];
    const float* ln1g    = (const float*)d_in[8];
    const float* ln1b    = (const float*)d_in[9];
    const float* ln2g    = (const float*)d_in[10];
    const float* ln2b    = (const float*)d_in[11];
    const float* w1      = (const float*)d_in[12];
    const float* fb1     = (const float*)d_in[13];
    const float* w2      = (const float*)d_in[14];
    const float* fb2     = (const float*)d_in[15];
    const float* cw1     = (const float*)d_in[16];
    const float* cb1     = (const float*)d_in[17];
    const float* cw2     = (const float*)d_in[18];
    const float* cb2     = (const float*)d_in[19];
    const float* cw3     = (const float*)d_in[20];
    const float* cb3     = (const float*)d_in[21];
    const float* cw4     = (const float*)d_in[22];
    const float* cb4     = (const float*)d_in[23];

    float *poolp;
    __nv_bfloat16 *hbf, *attnbf, *qh, *kh, *vh, *wh;
    cudaGetSymbolAddress((void**)&poolp, g_poolp);
    cudaGetSymbolAddress((void**)&hbf, g_hbf);
    cudaGetSymbolAddress((void**)&attnbf, g_attnbf);
    cudaGetSymbolAddress((void**)&qh, g_qh);
    cudaGetSymbolAddress((void**)&kh, g_kh);
    cudaGetSymbolAddress((void**)&vh, g_vh);
    cudaGetSymbolAddress((void**)&wh, g_wh);

    cudaFuncSetAttribute(gemm_qkv3_kernel,
                         cudaFuncAttributeMaxDynamicSharedMemorySize, SMEM_MMA);
    cudaFuncSetAttribute(gemm_fused3_kernel,
                         cudaFuncAttributeMaxDynamicSharedMemorySize, SMEM_MMA);
    cudaFuncSetAttribute(attn_mma_kernel,
                         cudaFuncAttributeMaxDynamicSharedMemorySize, ATT_SMEM);

    wconv_embed_kernel<<<2176, 256>>>(ipw, ow, w1, w2, wh,
                                      x, embed_w, embed_b, hbf);

    for (int i = 0; i < 3; i++) {
        const __nv_bfloat16* whb = wh + (size_t)i * 6 * WTILE;
        const float* ipb_i = ipb + (size_t)i * 3 * NE;
        const float* ob_i  = ob  + (size_t)i * NE;
        const float* l1g   = ln1g + (size_t)i * NE;
        const float* l1b   = ln1b + (size_t)i * NE;
        const float* l2g   = ln2g + (size_t)i * NE;
        const float* l2b   = ln2b + (size_t)i * NE;
        const float* fb1_i = fb1 + (size_t)i * NE;
        const float* fb2_i = fb2 + (size_t)i * NE;

        gemm_qkv3_kernel<<<dim3(1, 256), 256, SMEM_MMA>>>(hbf, whb, ipb_i,
                                                          qh, kh, vh);
        attn_mma_kernel<<<1024, 256, ATT_SMEM>>>(qh, kh, vh, attnbf);
        gemm_fused3_kernel<<<dim3(1, 256), 256, SMEM_MMA>>>(
            attnbf, whb, ob_i, fb1_i, fb2_i, l1g, l1b, l2g, l2b, hbf);
    }

    pool1_kernel<<<dim3(8, NB), 128>>>(hbf, mask, poolp);
    cls_kernel<<<NB, 256>>>(poolp, cw1, cb1, cw2, cb2, cw3, cb3, cw4, cb4,
                            (float*)d_out);
}